// round 8
// baseline (speedup 1.0000x reference)
#include <cuda_runtime.h>

#define N_NODES 50000
#define N_EDGES 1600000
#define HID 64
#define FULL 0xffffffffu

// ---- packed f32x2 helpers ----------------------------------------------------
#define FMA2(d, a, b, c) \
    asm("fma.rn.f32x2 %0, %1, %2, %3;" : "=l"(d) : "l"(a), "l"(b), "l"(c))
#define PACKF2(d, x, y) \
    asm("mov.b64 %0, {%1, %2};" : "=l"(d) : "r"(__float_as_uint(x)), "r"(__float_as_uint(y)))

__device__ __forceinline__ float relu_sum(unsigned long long a) {
    unsigned int lo, hi;
    asm("mov.b64 {%0, %1}, %2;" : "=r"(lo), "=r"(hi) : "l"(a));
    return fmaxf(__uint_as_float(lo) + __uint_as_float(hi), 0.f);
}

// ---------------- scratch (device globals; no allocation allowed) -------------
__device__ int   g_deg[N_NODES];
__device__ int   g_cursor[N_NODES];
__device__ int   g_rowstart[N_NODES + 1];
__device__ int   g_ssrc[N_EDGES];
__device__ float g_z0[N_NODES];
__device__ __align__(16) float g_ya[N_NODES * HID];   // fp32 activations, buffer A
__device__ __align__(16) float g_yb[N_NODES * HID];   // fp32 activations, buffer B
__device__ float g_stats[2 * HID];
__device__ float g_scale[HID];
__device__ float g_shift[HID];

// ---------------- CSR build ---------------------------------------------------
__global__ void k_zero() {
    int i = blockIdx.x * blockDim.x + threadIdx.x;
    if (i < N_NODES) g_deg[i] = 0;
    if (i < 2 * HID) g_stats[i] = 0.f;
}

__global__ void k_hist(const int* __restrict__ dst) {
    int e8 = blockIdx.x * blockDim.x + threadIdx.x;
    if (e8 < N_EDGES / 8) {
        int4 d0 = ((const int4*)dst)[2 * e8];
        int4 d1 = ((const int4*)dst)[2 * e8 + 1];
        atomicAdd(&g_deg[d0.x], 1); atomicAdd(&g_deg[d0.y], 1);
        atomicAdd(&g_deg[d0.z], 1); atomicAdd(&g_deg[d0.w], 1);
        atomicAdd(&g_deg[d1.x], 1); atomicAdd(&g_deg[d1.y], 1);
        atomicAdd(&g_deg[d1.z], 1); atomicAdd(&g_deg[d1.w], 1);
    }
}

__global__ void k_scan() {
    __shared__ int part[1024];
    const int CH = (N_NODES + 1023) / 1024;   // 49
    int tid = threadIdx.x;
    int base = tid * CH;
    int s = 0;
    for (int j = 0; j < CH; j++) {
        int idx = base + j;
        if (idx < N_NODES) s += g_deg[idx];
    }
    part[tid] = s;
    __syncthreads();
    for (int off = 1; off < 1024; off <<= 1) {
        int v = (tid >= off) ? part[tid - off] : 0;
        __syncthreads();
        if (tid >= off) part[tid] += v;
        __syncthreads();
    }
    int run = (tid > 0) ? part[tid - 1] : 0;
    for (int j = 0; j < CH; j++) {
        int idx = base + j;
        if (idx < N_NODES) {
            g_rowstart[idx] = run;
            g_cursor[idx]   = run;
            run += g_deg[idx];
        }
    }
    if (tid == 1023) g_rowstart[N_NODES] = part[1023];
}

__global__ void k_permute(const int* __restrict__ src, const int* __restrict__ dst) {
    int e8 = blockIdx.x * blockDim.x + threadIdx.x;
    if (e8 < N_EDGES / 8) {
        int4 d0 = ((const int4*)dst)[2 * e8];
        int4 d1 = ((const int4*)dst)[2 * e8 + 1];
        int4 s0 = ((const int4*)src)[2 * e8];
        int4 s1 = ((const int4*)src)[2 * e8 + 1];
        g_ssrc[atomicAdd(&g_cursor[d0.x], 1)] = s0.x;
        g_ssrc[atomicAdd(&g_cursor[d0.y], 1)] = s0.y;
        g_ssrc[atomicAdd(&g_cursor[d0.z], 1)] = s0.z;
        g_ssrc[atomicAdd(&g_cursor[d0.w], 1)] = s0.w;
        g_ssrc[atomicAdd(&g_cursor[d1.x], 1)] = s1.x;
        g_ssrc[atomicAdd(&g_cursor[d1.y], 1)] = s1.y;
        g_ssrc[atomicAdd(&g_cursor[d1.z], 1)] = s1.z;
        g_ssrc[atomicAdd(&g_cursor[d1.w], 1)] = s1.w;
    }
}

// ---------------- layer 1 aggregation (scalar features) ----------------------
__global__ void k_agg1(const float* __restrict__ x, const float* __restrict__ eps) {
    int gw = (blockIdx.x * blockDim.x + threadIdx.x) >> 5;
    if (gw >= N_NODES) return;
    int lane = threadIdx.x & 31;
    int beg = g_rowstart[gw], end = g_rowstart[gw + 1];
    float s = 0.f;
    for (int e = beg + lane; e < end; e += 32) s += x[g_ssrc[e]];
#pragma unroll
    for (int off = 16; off; off >>= 1) s += __shfl_down_sync(FULL, s, off);
    if (lane == 0) g_z0[gw] = fmaf(1.f + eps[0], x[gw], s);
}

// ---------------- fused layer: gather(BN-folded) + 2-layer MLP (FFMA2) -------
// Block = 256 threads. Group = 16 nodes: each of 8 warps gathers 2 nodes
// (interleaved edges for 32 LDG.128 in flight), z staged in smem, then
// 4 subgroups x 64 output-threads run the MLP with smem weights + f32x2 FMA.
__global__ void __launch_bounds__(256, 3) k_layer(
    const float* __restrict__ eps, int layer, int flip,
    const float* __restrict__ W1, const float* __restrict__ b1,
    const float* __restrict__ W2, const float* __restrict__ b2)
{
    __shared__ __align__(16) float w1t[HID * 66];   // [o][k], stride 66 floats
    __shared__ __align__(16) float w2t[HID * 66];
    __shared__ __align__(16) float zsh[16 * HID];
    __shared__ __align__(16) float tsh[16 * HID];
    __shared__ float red[2][256];

    const float* __restrict__ Yin  = flip ? (const float*)g_yb : (const float*)g_ya;
    float* __restrict__ Yout       = flip ? g_ya : g_yb;

    int tid = threadIdx.x;
    for (int i = tid; i < HID * HID; i += 256) {
        int k = i >> 6, oc = i & 63;
        w1t[oc * 66 + k] = W1[i];
        w2t[oc * 66 + k] = W2[i];
    }
    int o = tid & 63, sg = tid >> 6;
    int w = tid >> 5, lane = tid & 31;
    int half = lane >> 4, lq = lane & 15;
    float b1o = b1[o], b2o = b2[o];
    float ep = 1.f + eps[layer];
    __syncthreads();

    const float4* __restrict__ Y4 = (const float4*)Yin;
    const unsigned long long* zshu = (const unsigned long long*)zsh;
    const unsigned long long* tshu = (const unsigned long long*)tsh;
    const unsigned long long* w1u  = (const unsigned long long*)w1t;
    const unsigned long long* w2u  = (const unsigned long long*)w2t;

    float ssum = 0.f, ssq = 0.f;
    for (int g = blockIdx.x; g < N_NODES / 16; g += gridDim.x) {
        int node0 = g * 16;
        // ---- gather phase: warp w handles nodes nA = node0+2w, nB = nA+1
        int nA = node0 + 2 * w;
        int begA = g_rowstart[nA],     endA = g_rowstart[nA + 1];
        int begB = endA,               endB = g_rowstart[nA + 2];
        begB = g_rowstart[nA + 1];
        int degA = endA - begA, degB = endB - begB;
        float4 aA = make_float4(0.f, 0.f, 0.f, 0.f);
        float4 aB = make_float4(0.f, 0.f, 0.f, 0.f);
        int mdeg = max(degA, degB);
        for (int base = 0; base < mdeg; base += 32) {
            int cA = degA - base, cB = degB - base;
            int sA = (cA > 0) ? g_ssrc[begA + base + min(lane, cA - 1)] : 0;
            int sB = (cB > 0) ? g_ssrc[begB + base + min(lane, cB - 1)] : 0;
            if ((cA >= 32) && (cB >= 32)) {
#pragma unroll 8
                for (int j = 0; j < 16; j++) {
                    int eA = __shfl_sync(FULL, sA, 2 * j + half);
                    int eB = __shfl_sync(FULL, sB, 2 * j + half);
                    float4 vA = Y4[eA * 16 + lq];
                    float4 vB = Y4[eB * 16 + lq];
                    aA.x += vA.x; aA.y += vA.y; aA.z += vA.z; aA.w += vA.w;
                    aB.x += vB.x; aB.y += vB.y; aB.z += vB.z; aB.w += vB.w;
                }
            } else {
                int lim = min(max(cA, cB), 32);
                for (int j = 0; 2 * j < lim; j++) {
                    int e = 2 * j + half;
                    int eA = __shfl_sync(FULL, sA, e);
                    int eB = __shfl_sync(FULL, sB, e);
                    if (e < cA) {
                        float4 v = Y4[eA * 16 + lq];
                        aA.x += v.x; aA.y += v.y; aA.z += v.z; aA.w += v.w;
                    }
                    if (e < cB) {
                        float4 v = Y4[eB * 16 + lq];
                        aB.x += v.x; aB.y += v.y; aB.z += v.z; aB.w += v.w;
                    }
                }
            }
        }
        // combine half-warps (each half summed complementary edges)
        aA.x += __shfl_xor_sync(FULL, aA.x, 16);
        aA.y += __shfl_xor_sync(FULL, aA.y, 16);
        aA.z += __shfl_xor_sync(FULL, aA.z, 16);
        aA.w += __shfl_xor_sync(FULL, aA.w, 16);
        aB.x += __shfl_xor_sync(FULL, aB.x, 16);
        aB.y += __shfl_xor_sync(FULL, aB.y, 16);
        aB.z += __shfl_xor_sync(FULL, aB.z, 16);
        aB.w += __shfl_xor_sync(FULL, aB.w, 16);
        {
            // half 0 lanes finalize nA, half 1 lanes finalize nB
            int n = nA + half;
            float4 acc = (half == 0) ? aA : aB;
            float dg = ep + (float)((half == 0) ? degA : degB);
            float4 ys = Y4[n * 16 + lq];
            float4 sc = ((const float4*)g_scale)[lq];
            float4 sh = ((const float4*)g_shift)[lq];
            float4 z;
            z.x = sc.x * fmaf(ep, ys.x, acc.x) + sh.x * dg;
            z.y = sc.y * fmaf(ep, ys.y, acc.y) + sh.y * dg;
            z.z = sc.z * fmaf(ep, ys.z, acc.z) + sh.z * dg;
            z.w = sc.w * fmaf(ep, ys.w, acc.w) + sh.w * dg;
            ((float4*)zsh)[(n - node0) * 16 + lq] = z;
        }
        __syncthreads();   // S1: zsh complete

        // ---- MLP layer 1: subgroup sg handles local nodes l0..l0+3 ----
        int l0 = sg * 4;
        unsigned long long ac0, ac1, ac2, ac3;
        PACKF2(ac0, b1o, 0.f); PACKF2(ac1, b1o, 0.f);
        PACKF2(ac2, b1o, 0.f); PACKF2(ac3, b1o, 0.f);
        {
            const unsigned long long* wrow = w1u + o * 33;
            const unsigned long long* z0p = zshu + (l0 + 0) * 32;
            const unsigned long long* z1p = zshu + (l0 + 1) * 32;
            const unsigned long long* z2p = zshu + (l0 + 2) * 32;
            const unsigned long long* z3p = zshu + (l0 + 3) * 32;
#pragma unroll 8
            for (int kp = 0; kp < 32; kp++) {
                unsigned long long wv = wrow[kp];
                FMA2(ac0, z0p[kp], wv, ac0);
                FMA2(ac1, z1p[kp], wv, ac1);
                FMA2(ac2, z2p[kp], wv, ac2);
                FMA2(ac3, z3p[kp], wv, ac3);
            }
        }
        tsh[(l0 + 0) * HID + o] = relu_sum(ac0);
        tsh[(l0 + 1) * HID + o] = relu_sum(ac1);
        tsh[(l0 + 2) * HID + o] = relu_sum(ac2);
        tsh[(l0 + 3) * HID + o] = relu_sum(ac3);
        __syncthreads();   // S2: tsh complete, zsh free

        // ---- MLP layer 2 ----
        PACKF2(ac0, b2o, 0.f); PACKF2(ac1, b2o, 0.f);
        PACKF2(ac2, b2o, 0.f); PACKF2(ac3, b2o, 0.f);
        {
            const unsigned long long* wrow = w2u + o * 33;
            const unsigned long long* t0p = tshu + (l0 + 0) * 32;
            const unsigned long long* t1p = tshu + (l0 + 1) * 32;
            const unsigned long long* t2p = tshu + (l0 + 2) * 32;
            const unsigned long long* t3p = tshu + (l0 + 3) * 32;
#pragma unroll 8
            for (int kp = 0; kp < 32; kp++) {
                unsigned long long wv = wrow[kp];
                FMA2(ac0, t0p[kp], wv, ac0);
                FMA2(ac1, t1p[kp], wv, ac1);
                FMA2(ac2, t2p[kp], wv, ac2);
                FMA2(ac3, t3p[kp], wv, ac3);
            }
        }
        float y0 = relu_sum(ac0), y1 = relu_sum(ac1);
        float y2 = relu_sum(ac2), y3 = relu_sum(ac3);
        Yout[(node0 + l0 + 0) * HID + o] = y0;
        Yout[(node0 + l0 + 1) * HID + o] = y1;
        Yout[(node0 + l0 + 2) * HID + o] = y2;
        Yout[(node0 + l0 + 3) * HID + o] = y3;
        ssum += y0 + y1 + y2 + y3;
        ssq = fmaf(y0, y0, ssq); ssq = fmaf(y1, y1, ssq);
        ssq = fmaf(y2, y2, ssq); ssq = fmaf(y3, y3, ssq);
    }
    red[0][tid] = ssum; red[1][tid] = ssq;
    __syncthreads();
    if (tid < HID) {
        atomicAdd(&g_stats[tid],
                  red[0][tid] + red[0][tid + 64] + red[0][tid + 128] + red[0][tid + 192]);
        atomicAdd(&g_stats[HID + tid],
                  red[1][tid] + red[1][tid + 64] + red[1][tid + 128] + red[1][tid + 192]);
    }
}

// ---------------- MLP for layer 1 (scalar -> 64 -> 64), writes g_ya ----------
#define MLP_NPB 8
__global__ void __launch_bounds__(128, 3) k_mlp1(
    const float* __restrict__ w1a, const float* __restrict__ b1a,
    const float* __restrict__ W2, const float* __restrict__ b2)
{
    __shared__ float zs[MLP_NPB];
    __shared__ float tsh[MLP_NPB * HID];
    __shared__ float red[2][128];

    int tid = threadIdx.x;
    int o = tid & 63, sg = tid >> 6;

    float w2r[HID];
#pragma unroll
    for (int k = 0; k < HID; k++) w2r[k] = W2[k * HID + o];
    float w1o = w1a[o], b1o = b1a[o], b2o = b2[o];

    const float4* tsh4 = (const float4*)tsh;

    float ssum = 0.f, ssq = 0.f;
    const int ngroups = N_NODES / MLP_NPB;
    for (int g = blockIdx.x; g < ngroups; g += gridDim.x) {
        int node0 = g * MLP_NPB;
        if (tid < MLP_NPB) zs[tid] = g_z0[node0 + tid];
        __syncthreads();
        tsh[(sg * 4 + 0) * HID + o] = fmaxf(fmaf(zs[sg * 4 + 0], w1o, b1o), 0.f);
        tsh[(sg * 4 + 1) * HID + o] = fmaxf(fmaf(zs[sg * 4 + 1], w1o, b1o), 0.f);
        tsh[(sg * 4 + 2) * HID + o] = fmaxf(fmaf(zs[sg * 4 + 2], w1o, b1o), 0.f);
        tsh[(sg * 4 + 3) * HID + o] = fmaxf(fmaf(zs[sg * 4 + 3], w1o, b1o), 0.f);
        __syncthreads();

        float ac0 = b2o, ac1 = b2o, ac2 = b2o, ac3 = b2o;
        {
            int r0 = (sg * 4 + 0) * 16, r1 = (sg * 4 + 1) * 16;
            int r2 = (sg * 4 + 2) * 16, r3 = (sg * 4 + 3) * 16;
#pragma unroll
            for (int k4 = 0; k4 < 16; k4++) {
                float4 t0 = tsh4[r0 + k4];
                float4 t1 = tsh4[r1 + k4];
                float4 t2 = tsh4[r2 + k4];
                float4 t3 = tsh4[r3 + k4];
                float wa = w2r[4 * k4], wb = w2r[4 * k4 + 1];
                float wc = w2r[4 * k4 + 2], wd = w2r[4 * k4 + 3];
                ac0 = fmaf(t0.x, wa, ac0); ac1 = fmaf(t1.x, wa, ac1);
                ac2 = fmaf(t2.x, wa, ac2); ac3 = fmaf(t3.x, wa, ac3);
                ac0 = fmaf(t0.y, wb, ac0); ac1 = fmaf(t1.y, wb, ac1);
                ac2 = fmaf(t2.y, wb, ac2); ac3 = fmaf(t3.y, wb, ac3);
                ac0 = fmaf(t0.z, wc, ac0); ac1 = fmaf(t1.z, wc, ac1);
                ac2 = fmaf(t2.z, wc, ac2); ac3 = fmaf(t3.z, wc, ac3);
                ac0 = fmaf(t0.w, wd, ac0); ac1 = fmaf(t1.w, wd, ac1);
                ac2 = fmaf(t2.w, wd, ac2); ac3 = fmaf(t3.w, wd, ac3);
            }
        }
        float y0 = fmaxf(ac0, 0.f), y1 = fmaxf(ac1, 0.f);
        float y2 = fmaxf(ac2, 0.f), y3 = fmaxf(ac3, 0.f);
        g_ya[(node0 + sg * 4 + 0) * HID + o] = y0;
        g_ya[(node0 + sg * 4 + 1) * HID + o] = y1;
        g_ya[(node0 + sg * 4 + 2) * HID + o] = y2;
        g_ya[(node0 + sg * 4 + 3) * HID + o] = y3;
        ssum += y0 + y1 + y2 + y3;
        ssq  += y0 * y0 + y1 * y1 + y2 * y2 + y3 * y3;
        __syncthreads();
    }
    red[0][tid] = ssum; red[1][tid] = ssq;
    __syncthreads();
    if (tid < HID) {
        atomicAdd(&g_stats[tid],       red[0][tid] + red[0][tid + 64]);
        atomicAdd(&g_stats[HID + tid], red[1][tid] + red[1][tid + 64]);
    }
}

// ---------------- BN stats -> affine (scale/shift), reset stats ---------------
__global__ void k_bn(const float* __restrict__ gamma, const float* __restrict__ beta) {
    int f = threadIdx.x;
    if (f < HID) {
        float s = g_stats[f], q = g_stats[HID + f];
        const float inv = 1.f / (float)N_NODES;
        float mu = s * inv;
        float var = q * inv - mu * mu;
        float rstd = rsqrtf(var + 1e-5f);
        float sc = gamma[f] * rstd;
        g_scale[f] = sc;
        g_shift[f] = beta[f] - mu * sc;
        g_stats[f] = 0.f;
        g_stats[HID + f] = 0.f;
    }
}

// ---------------- final: out = (yb*sc+sh) @ fc_w + fc_b -----------------------
__global__ void k_fc(const float* __restrict__ fcw, const float* __restrict__ fcb,
                     float* __restrict__ out) {
    int gw = (blockIdx.x * blockDim.x + threadIdx.x) >> 5;
    if (gw >= N_NODES) return;
    int lane = threadIdx.x & 31;
    float2 y  = ((const float2*)g_yb)[gw * 32 + lane];
    float2 sc = ((const float2*)g_scale)[lane];
    float2 sh = ((const float2*)g_shift)[lane];
    float2 fw = ((const float2*)fcw)[lane];
    float p = fmaf(fmaf(y.x, sc.x, sh.x), fw.x,
                   fmaf(y.y, sc.y, sh.y) * fw.y);
#pragma unroll
    for (int off = 16; off; off >>= 1) p += __shfl_down_sync(FULL, p, off);
    if (lane == 0) out[gw] = p + fcb[0];
}

// ---------------- launch ------------------------------------------------------
extern "C" void kernel_launch(void* const* d_in, const int* in_sizes, int n_in,
                              void* d_out, int out_size) {
    const float* x      = (const float*)d_in[0];
    const int*   ei     = (const int*)  d_in[1];
    const int*   src    = ei;
    const int*   dst    = ei + N_EDGES;
    const float* w1a    = (const float*)d_in[2];
    const float* b1a    = (const float*)d_in[3];
    const float* w2a    = (const float*)d_in[4];
    const float* b2a    = (const float*)d_in[5];
    const float* w1s    = (const float*)d_in[6];
    const float* b1s    = (const float*)d_in[7];
    const float* w2s    = (const float*)d_in[8];
    const float* b2s    = (const float*)d_in[9];
    const float* eps    = (const float*)d_in[10];
    const float* gammas = (const float*)d_in[11];
    const float* betas  = (const float*)d_in[12];
    const float* fcw    = (const float*)d_in[13];
    const float* fcb    = (const float*)d_in[14];
    float* out = (float*)d_out;

    const int EB8 = (N_EDGES / 8 + 255) / 256;     // 782
    const int WB  = (N_NODES * 32 + 255) / 256;    // 6250 (warp per node)
    const int MLP_GRID = 444;
    const int LAYER_GRID = 444;                    // 148 SMs x 3 blocks

    // CSR build (every replay; all scratch state re-derived)
    k_zero<<<(N_NODES + 255) / 256, 256>>>();
    k_hist<<<EB8, 256>>>(dst);
    k_scan<<<1, 1024>>>();
    k_permute<<<EB8, 256>>>(src, dst);

    // layer 1 (scalar input) -> g_ya
    k_agg1<<<WB, 256>>>(x, eps);
    k_mlp1<<<MLP_GRID, 128>>>(w1a, b1a, w2a, b2a);
    k_bn<<<1, 64>>>(gammas, betas);

    // layers 2-4: fused gather+MLP, double-buffered y (ya->yb->ya->yb)
    for (int l = 0; l < 3; l++) {
        k_layer<<<LAYER_GRID, 256>>>(eps, l + 1, l & 1,
                                     w1s + l * HID * HID, b1s + l * HID,
                                     w2s + l * HID * HID, b2s + l * HID);
        k_bn<<<1, 64>>>(gammas + (l + 1) * HID, betas + (l + 1) * HID);
    }

    // final FC with BN folded (layer-4 output lives in g_yb)
    k_fc<<<WB, 256>>>(fcw, fcb, out);
}

// round 9
// speedup vs baseline: 1.1218x; 1.1218x over previous
#include <cuda_runtime.h>

#define N_NODES 50000
#define N_EDGES 1600000
#define HID 64
#define FULL 0xffffffffu
#define BN_EPS 1e-5f
#define INV_N (1.f / (float)N_NODES)

// ---- packed f32x2 helpers ----------------------------------------------------
#define FMA2(d, a, b, c) \
    asm("fma.rn.f32x2 %0, %1, %2, %3;" : "=l"(d) : "l"(a), "l"(b), "l"(c))
#define PACKF2(d, x, y) \
    asm("mov.b64 %0, {%1, %2};" : "=l"(d) : "r"(__float_as_uint(x)), "r"(__float_as_uint(y)))

__device__ __forceinline__ float relu_sum(unsigned long long a) {
    unsigned int lo, hi;
    asm("mov.b64 {%0, %1}, %2;" : "=r"(lo), "=r"(hi) : "l"(a));
    return fmaxf(__uint_as_float(lo) + __uint_as_float(hi), 0.f);
}

// ---------------- scratch (device globals; no allocation allowed) -------------
__device__ int   g_deg[N_NODES];
__device__ int   g_cursor[N_NODES];
__device__ int   g_rowstart[N_NODES + 1];
__device__ int   g_ssrc[N_EDGES];
__device__ float g_z0[N_NODES];
__device__ __align__(16) float g_z[N_NODES * HID];
__device__ __align__(16) float g_y[N_NODES * HID];
__device__ __align__(16) float g_stats[4 * 2 * HID];   // per-layer: [sum(64)|sq(64)]

// ---------------- CSR build ---------------------------------------------------
__global__ void k_zero() {
    int i = blockIdx.x * blockDim.x + threadIdx.x;
    if (i < N_NODES) g_deg[i] = 0;
    if (i < 4 * 2 * HID) g_stats[i] = 0.f;
}

__global__ void k_hist(const int* __restrict__ dst) {
    int e8 = blockIdx.x * blockDim.x + threadIdx.x;
    if (e8 < N_EDGES / 8) {
        int4 d0 = ((const int4*)dst)[2 * e8];
        int4 d1 = ((const int4*)dst)[2 * e8 + 1];
        atomicAdd(&g_deg[d0.x], 1); atomicAdd(&g_deg[d0.y], 1);
        atomicAdd(&g_deg[d0.z], 1); atomicAdd(&g_deg[d0.w], 1);
        atomicAdd(&g_deg[d1.x], 1); atomicAdd(&g_deg[d1.y], 1);
        atomicAdd(&g_deg[d1.z], 1); atomicAdd(&g_deg[d1.w], 1);
    }
}

__global__ void k_scan() {
    __shared__ int part[1024];
    const int CH = (N_NODES + 1023) / 1024;   // 49
    int tid = threadIdx.x;
    int base = tid * CH;
    int s = 0;
    for (int j = 0; j < CH; j++) {
        int idx = base + j;
        if (idx < N_NODES) s += g_deg[idx];
    }
    part[tid] = s;
    __syncthreads();
    for (int off = 1; off < 1024; off <<= 1) {
        int v = (tid >= off) ? part[tid - off] : 0;
        __syncthreads();
        if (tid >= off) part[tid] += v;
        __syncthreads();
    }
    int run = (tid > 0) ? part[tid - 1] : 0;
    for (int j = 0; j < CH; j++) {
        int idx = base + j;
        if (idx < N_NODES) {
            g_rowstart[idx] = run;
            g_cursor[idx]   = run;
            run += g_deg[idx];
        }
    }
    if (tid == 1023) g_rowstart[N_NODES] = part[1023];
}

__global__ void k_permute(const int* __restrict__ src, const int* __restrict__ dst) {
    int e8 = blockIdx.x * blockDim.x + threadIdx.x;
    if (e8 < N_EDGES / 8) {
        int4 d0 = ((const int4*)dst)[2 * e8];
        int4 d1 = ((const int4*)dst)[2 * e8 + 1];
        int4 s0 = ((const int4*)src)[2 * e8];
        int4 s1 = ((const int4*)src)[2 * e8 + 1];
        g_ssrc[atomicAdd(&g_cursor[d0.x], 1)] = s0.x;
        g_ssrc[atomicAdd(&g_cursor[d0.y], 1)] = s0.y;
        g_ssrc[atomicAdd(&g_cursor[d0.z], 1)] = s0.z;
        g_ssrc[atomicAdd(&g_cursor[d0.w], 1)] = s0.w;
        g_ssrc[atomicAdd(&g_cursor[d1.x], 1)] = s1.x;
        g_ssrc[atomicAdd(&g_cursor[d1.y], 1)] = s1.y;
        g_ssrc[atomicAdd(&g_cursor[d1.z], 1)] = s1.z;
        g_ssrc[atomicAdd(&g_cursor[d1.w], 1)] = s1.w;
    }
}

// ---------------- layer 1 aggregation (scalar features) ----------------------
__global__ void k_agg1(const float* __restrict__ x, const float* __restrict__ eps) {
    int gw = (blockIdx.x * blockDim.x + threadIdx.x) >> 5;
    if (gw >= N_NODES) return;
    int lane = threadIdx.x & 31;
    int beg = g_rowstart[gw], end = g_rowstart[gw + 1];
    float s = 0.f;
    for (int e = beg + lane; e < end; e += 32) s += x[g_ssrc[e]];
#pragma unroll
    for (int off = 16; off; off >>= 1) s += __shfl_down_sync(FULL, s, off);
    if (lane == 0) g_z0[gw] = fmaf(1.f + eps[0], x[gw], s);
}

// ---------------- aggregation, BN(prev layer) folded in, affine inline -------
// z[i][f] = sc[f]*((1+eps)*y[i][f] + sum_j y[j][f]) + sh[f]*((1+eps)+deg)
// sc/sh computed from g_stats[slot] (+ gamma/beta) on the fly.
__global__ void k_agg(const float* __restrict__ eps, int layer, int slot,
                      const float* __restrict__ gamma,
                      const float* __restrict__ beta) {
    int gw = (blockIdx.x * blockDim.x + threadIdx.x) >> 5;
    if (gw >= N_NODES) return;
    int lane = threadIdx.x & 31;
    int half = lane >> 4, lq = lane & 15;
    int beg = g_rowstart[gw], end = g_rowstart[gw + 1];
    const float4* __restrict__ Y4 = (const float4*)g_y;

    float4 a = make_float4(0.f, 0.f, 0.f, 0.f);
    for (int e0 = beg; e0 < end; e0 += 32) {
        int cnt = end - e0; if (cnt > 32) cnt = 32;
        int s = g_ssrc[e0 + min(lane, cnt - 1)];
        if (cnt == 32) {
#pragma unroll
            for (int j = 0; j < 32; j += 2) {
                int sj = __shfl_sync(FULL, s, j + half);
                float4 v = Y4[sj * 16 + lq];
                a.x += v.x; a.y += v.y; a.z += v.z; a.w += v.w;
            }
        } else {
            for (int j = 0; j < cnt; j += 2) {
                int e = j + half;
                int sj = __shfl_sync(FULL, s, min(e, 31));
                if (e < cnt) {
                    float4 v = Y4[sj * 16 + lq];
                    a.x += v.x; a.y += v.y; a.z += v.z; a.w += v.w;
                }
            }
        }
    }
    a.x += __shfl_xor_sync(FULL, a.x, 16);
    a.y += __shfl_xor_sync(FULL, a.y, 16);
    a.z += __shfl_xor_sync(FULL, a.z, 16);
    a.w += __shfl_xor_sync(FULL, a.w, 16);

    if (half == 0) {
        float ep = 1.f + eps[layer];
        float dg = ep + (float)(end - beg);
        const float* st = g_stats + slot * 128;
        float4 s4 = ((const float4*)st)[lq];
        float4 q4 = ((const float4*)(st + 64))[lq];
        float4 gm = ((const float4*)gamma)[lq];
        float4 bt = ((const float4*)beta)[lq];
        float4 mu, sc, sh;
        mu.x = s4.x * INV_N; mu.y = s4.y * INV_N;
        mu.z = s4.z * INV_N; mu.w = s4.w * INV_N;
        sc.x = gm.x * rsqrtf(fmaf(q4.x, INV_N, -mu.x * mu.x) + BN_EPS);
        sc.y = gm.y * rsqrtf(fmaf(q4.y, INV_N, -mu.y * mu.y) + BN_EPS);
        sc.z = gm.z * rsqrtf(fmaf(q4.z, INV_N, -mu.z * mu.z) + BN_EPS);
        sc.w = gm.w * rsqrtf(fmaf(q4.w, INV_N, -mu.w * mu.w) + BN_EPS);
        sh.x = bt.x - mu.x * sc.x; sh.y = bt.y - mu.y * sc.y;
        sh.z = bt.z - mu.z * sc.z; sh.w = bt.w - mu.w * sc.w;
        float4 ys = Y4[gw * 16 + lq];
        float4 z;
        z.x = sc.x * fmaf(ep, ys.x, a.x) + sh.x * dg;
        z.y = sc.y * fmaf(ep, ys.y, a.y) + sh.y * dg;
        z.z = sc.z * fmaf(ep, ys.z, a.z) + sh.z * dg;
        z.w = sc.w * fmaf(ep, ys.w, a.w) + sh.w * dg;
        ((float4*)g_z)[gw * 16 + lq] = z;
    }
}

// ---------------- MLP: FFMA2, packed register weights, broadcast LDS.128 -----
// 128 threads = 2 subgroups x 64 outputs; 8 nodes per iteration; 4 nodes/thread.
__global__ void __launch_bounds__(128, 2) k_mlp(
    const float* __restrict__ W1, const float* __restrict__ b1,
    const float* __restrict__ W2, const float* __restrict__ b2, int slot)
{
    __shared__ __align__(16) float zsh[8 * HID];
    __shared__ __align__(16) float tsh[8 * HID];
    __shared__ float red[2][128];

    int tid = threadIdx.x;
    int o = tid & 63, sg = tid >> 6;

    // packed weight columns: w1p[j] = (W1[2j][o], W1[2j+1][o])
    unsigned long long w1p[32], w2p[32];
#pragma unroll
    for (int j = 0; j < 32; j++)
        PACKF2(w1p[j], W1[(2 * j) * HID + o], W1[(2 * j + 1) * HID + o]);
#pragma unroll
    for (int j = 0; j < 32; j++)
        PACKF2(w2p[j], W2[(2 * j) * HID + o], W2[(2 * j + 1) * HID + o]);
    float b1o = b1[o], b2o = b2[o];

    const ulonglong2* zshU = (const ulonglong2*)zsh;
    const ulonglong2* tshU = (const ulonglong2*)tsh;

    float ssum = 0.f, ssq = 0.f;
    const int ngroups = N_NODES / 8;      // 6250
    for (int g = blockIdx.x; g < ngroups; g += gridDim.x) {
        int node0 = g * 8;
        ((float4*)zsh)[tid] = ((const float4*)(g_z + node0 * HID))[tid];
        __syncthreads();

        int l0 = sg * 4;
        unsigned long long ac0, ac1, ac2, ac3;
        PACKF2(ac0, b1o, 0.f); PACKF2(ac1, b1o, 0.f);
        PACKF2(ac2, b1o, 0.f); PACKF2(ac3, b1o, 0.f);
        {
            const ulonglong2* z0 = zshU + (l0 + 0) * 16;
            const ulonglong2* z1 = zshU + (l0 + 1) * 16;
            const ulonglong2* z2 = zshU + (l0 + 2) * 16;
            const ulonglong2* z3 = zshU + (l0 + 3) * 16;
#pragma unroll
            for (int k4 = 0; k4 < 16; k4++) {
                ulonglong2 v0 = z0[k4], v1 = z1[k4], v2 = z2[k4], v3 = z3[k4];
                unsigned long long wA = w1p[2 * k4], wB = w1p[2 * k4 + 1];
                FMA2(ac0, v0.x, wA, ac0); FMA2(ac0, v0.y, wB, ac0);
                FMA2(ac1, v1.x, wA, ac1); FMA2(ac1, v1.y, wB, ac1);
                FMA2(ac2, v2.x, wA, ac2); FMA2(ac2, v2.y, wB, ac2);
                FMA2(ac3, v3.x, wA, ac3); FMA2(ac3, v3.y, wB, ac3);
            }
        }
        tsh[(l0 + 0) * HID + o] = relu_sum(ac0);
        tsh[(l0 + 1) * HID + o] = relu_sum(ac1);
        tsh[(l0 + 2) * HID + o] = relu_sum(ac2);
        tsh[(l0 + 3) * HID + o] = relu_sum(ac3);
        __syncthreads();

        PACKF2(ac0, b2o, 0.f); PACKF2(ac1, b2o, 0.f);
        PACKF2(ac2, b2o, 0.f); PACKF2(ac3, b2o, 0.f);
        {
            const ulonglong2* t0 = tshU + (l0 + 0) * 16;
            const ulonglong2* t1 = tshU + (l0 + 1) * 16;
            const ulonglong2* t2 = tshU + (l0 + 2) * 16;
            const ulonglong2* t3 = tshU + (l0 + 3) * 16;
#pragma unroll
            for (int k4 = 0; k4 < 16; k4++) {
                ulonglong2 v0 = t0[k4], v1 = t1[k4], v2 = t2[k4], v3 = t3[k4];
                unsigned long long wA = w2p[2 * k4], wB = w2p[2 * k4 + 1];
                FMA2(ac0, v0.x, wA, ac0); FMA2(ac0, v0.y, wB, ac0);
                FMA2(ac1, v1.x, wA, ac1); FMA2(ac1, v1.y, wB, ac1);
                FMA2(ac2, v2.x, wA, ac2); FMA2(ac2, v2.y, wB, ac2);
                FMA2(ac3, v3.x, wA, ac3); FMA2(ac3, v3.y, wB, ac3);
            }
        }
        float y0 = relu_sum(ac0), y1 = relu_sum(ac1);
        float y2 = relu_sum(ac2), y3 = relu_sum(ac3);
        g_y[(node0 + l0 + 0) * HID + o] = y0;
        g_y[(node0 + l0 + 1) * HID + o] = y1;
        g_y[(node0 + l0 + 2) * HID + o] = y2;
        g_y[(node0 + l0 + 3) * HID + o] = y3;
        ssum += y0 + y1 + y2 + y3;
        ssq = fmaf(y0, y0, ssq); ssq = fmaf(y1, y1, ssq);
        ssq = fmaf(y2, y2, ssq); ssq = fmaf(y3, y3, ssq);
    }
    red[0][tid] = ssum; red[1][tid] = ssq;
    __syncthreads();
    if (tid < HID) {
        atomicAdd(&g_stats[slot * 128 + tid],      red[0][tid] + red[0][tid + 64]);
        atomicAdd(&g_stats[slot * 128 + 64 + tid], red[1][tid] + red[1][tid + 64]);
    }
}

// ---------------- MLP for layer 1 (scalar -> 64 -> 64), stats slot 0 ---------
#define MLP_NPB 8
__global__ void __launch_bounds__(128, 3) k_mlp1(
    const float* __restrict__ w1a, const float* __restrict__ b1a,
    const float* __restrict__ W2, const float* __restrict__ b2)
{
    __shared__ float zs[MLP_NPB];
    __shared__ float tsh[MLP_NPB * HID];
    __shared__ float red[2][128];

    int tid = threadIdx.x;
    int o = tid & 63, sg = tid >> 6;

    float w2r[HID];
#pragma unroll
    for (int k = 0; k < HID; k++) w2r[k] = W2[k * HID + o];
    float w1o = w1a[o], b1o = b1a[o], b2o = b2[o];

    const float4* tsh4 = (const float4*)tsh;

    float ssum = 0.f, ssq = 0.f;
    const int ngroups = N_NODES / MLP_NPB;
    for (int g = blockIdx.x; g < ngroups; g += gridDim.x) {
        int node0 = g * MLP_NPB;
        if (tid < MLP_NPB) zs[tid] = g_z0[node0 + tid];
        __syncthreads();
        tsh[(sg * 4 + 0) * HID + o] = fmaxf(fmaf(zs[sg * 4 + 0], w1o, b1o), 0.f);
        tsh[(sg * 4 + 1) * HID + o] = fmaxf(fmaf(zs[sg * 4 + 1], w1o, b1o), 0.f);
        tsh[(sg * 4 + 2) * HID + o] = fmaxf(fmaf(zs[sg * 4 + 2], w1o, b1o), 0.f);
        tsh[(sg * 4 + 3) * HID + o] = fmaxf(fmaf(zs[sg * 4 + 3], w1o, b1o), 0.f);
        __syncthreads();

        float ac0 = b2o, ac1 = b2o, ac2 = b2o, ac3 = b2o;
        {
            int r0 = (sg * 4 + 0) * 16, r1 = (sg * 4 + 1) * 16;
            int r2 = (sg * 4 + 2) * 16, r3 = (sg * 4 + 3) * 16;
#pragma unroll
            for (int k4 = 0; k4 < 16; k4++) {
                float4 t0 = tsh4[r0 + k4];
                float4 t1 = tsh4[r1 + k4];
                float4 t2 = tsh4[r2 + k4];
                float4 t3 = tsh4[r3 + k4];
                float wa = w2r[4 * k4], wb = w2r[4 * k4 + 1];
                float wc = w2r[4 * k4 + 2], wd = w2r[4 * k4 + 3];
                ac0 = fmaf(t0.x, wa, ac0); ac1 = fmaf(t1.x, wa, ac1);
                ac2 = fmaf(t2.x, wa, ac2); ac3 = fmaf(t3.x, wa, ac3);
                ac0 = fmaf(t0.y, wb, ac0); ac1 = fmaf(t1.y, wb, ac1);
                ac2 = fmaf(t2.y, wb, ac2); ac3 = fmaf(t3.y, wb, ac3);
                ac0 = fmaf(t0.z, wc, ac0); ac1 = fmaf(t1.z, wc, ac1);
                ac2 = fmaf(t2.z, wc, ac2); ac3 = fmaf(t3.z, wc, ac3);
                ac0 = fmaf(t0.w, wd, ac0); ac1 = fmaf(t1.w, wd, ac1);
                ac2 = fmaf(t2.w, wd, ac2); ac3 = fmaf(t3.w, wd, ac3);
            }
        }
        float y0 = fmaxf(ac0, 0.f), y1 = fmaxf(ac1, 0.f);
        float y2 = fmaxf(ac2, 0.f), y3 = fmaxf(ac3, 0.f);
        g_y[(node0 + sg * 4 + 0) * HID + o] = y0;
        g_y[(node0 + sg * 4 + 1) * HID + o] = y1;
        g_y[(node0 + sg * 4 + 2) * HID + o] = y2;
        g_y[(node0 + sg * 4 + 3) * HID + o] = y3;
        ssum += y0 + y1 + y2 + y3;
        ssq  += y0 * y0 + y1 * y1 + y2 * y2 + y3 * y3;
        __syncthreads();
    }
    red[0][tid] = ssum; red[1][tid] = ssq;
    __syncthreads();
    if (tid < HID) {
        atomicAdd(&g_stats[tid],      red[0][tid] + red[0][tid + 64]);
        atomicAdd(&g_stats[64 + tid], red[1][tid] + red[1][tid + 64]);
    }
}

// ---------------- final: out = (BN3(y)) @ fc_w + fc_b, affine inline ---------
__global__ void k_fc(const float* __restrict__ fcw, const float* __restrict__ fcb,
                     const float* __restrict__ gamma, const float* __restrict__ beta,
                     float* __restrict__ out) {
    int gw = (blockIdx.x * blockDim.x + threadIdx.x) >> 5;
    if (gw >= N_NODES) return;
    int lane = threadIdx.x & 31;
    const float* st = g_stats + 3 * 128;
    float2 s2 = ((const float2*)st)[lane];
    float2 q2 = ((const float2*)(st + 64))[lane];
    float2 gm = ((const float2*)gamma)[lane];
    float2 bt = ((const float2*)beta)[lane];
    float mux = s2.x * INV_N, muy = s2.y * INV_N;
    float scx = gm.x * rsqrtf(fmaf(q2.x, INV_N, -mux * mux) + BN_EPS);
    float scy = gm.y * rsqrtf(fmaf(q2.y, INV_N, -muy * muy) + BN_EPS);
    float shx = bt.x - mux * scx;
    float shy = bt.y - muy * scy;
    float2 y  = ((const float2*)g_y)[gw * 32 + lane];
    float2 fw = ((const float2*)fcw)[lane];
    float p = fmaf(fmaf(y.x, scx, shx), fw.x,
                   fmaf(y.y, scy, shy) * fw.y);
#pragma unroll
    for (int off = 16; off; off >>= 1) p += __shfl_down_sync(FULL, p, off);
    if (lane == 0) out[gw] = p + fcb[0];
}

// ---------------- launch ------------------------------------------------------
extern "C" void kernel_launch(void* const* d_in, const int* in_sizes, int n_in,
                              void* d_out, int out_size) {
    const float* x      = (const float*)d_in[0];
    const int*   ei     = (const int*)  d_in[1];
    const int*   src    = ei;
    const int*   dst    = ei + N_EDGES;
    const float* w1a    = (const float*)d_in[2];
    const float* b1a    = (const float*)d_in[3];
    const float* w2a    = (const float*)d_in[4];
    const float* b2a    = (const float*)d_in[5];
    const float* w1s    = (const float*)d_in[6];
    const float* b1s    = (const float*)d_in[7];
    const float* w2s    = (const float*)d_in[8];
    const float* b2s    = (const float*)d_in[9];
    const float* eps    = (const float*)d_in[10];
    const float* gammas = (const float*)d_in[11];
    const float* betas  = (const float*)d_in[12];
    const float* fcw    = (const float*)d_in[13];
    const float* fcb    = (const float*)d_in[14];
    float* out = (float*)d_out;

    const int EB8 = (N_EDGES / 8 + 255) / 256;     // 782
    const int WB  = (N_NODES * 32 + 255) / 256;    // 6250 (warp per node)
    const int MLP1_GRID = 444;
    const int MLP_GRID  = 296;                     // 148 SMs x 2 blocks

    // CSR build (every replay; all scratch state re-derived)
    k_zero<<<(N_NODES + 255) / 256, 256>>>();
    k_hist<<<EB8, 256>>>(dst);
    k_scan<<<1, 1024>>>();
    k_permute<<<EB8, 256>>>(src, dst);

    // layer 1 (scalar input) -> y, stats slot 0
    k_agg1<<<WB, 256>>>(x, eps);
    k_mlp1<<<MLP1_GRID, 128>>>(w1a, b1a, w2a, b2a);

    // layers 2-4: agg (BN of layer l folded, affine inline) + FFMA2 MLP
    for (int l = 0; l < 3; l++) {
        k_agg<<<WB, 256>>>(eps, l + 1, l, gammas + l * HID, betas + l * HID);
        k_mlp<<<MLP_GRID, 128>>>(w1s + l * HID * HID, b1s + l * HID,
                                 w2s + l * HID * HID, b2s + l * HID, l + 1);
    }

    // final FC with BN(layer 4) folded, affine inline from stats slot 3
    k_fc<<<WB, 256>>>(fcw, fcb, gammas + 3 * HID, betas + 3 * HID, out);
}